// round 3
// baseline (speedup 1.0000x reference)
#include <cuda_runtime.h>
#include <math.h>

#define NN 20000
#define EE 320000
#define FI 128
#define HDIM 32
#define KORD 32
#define HD2 64   // z||h concatenated outputs

// ---------------- static device scratch (no runtime allocation) ----------------
__device__ int   g_deg[NN];
__device__ float g_dis[NN];
__device__ int   g_rowcnt[NN];
__device__ int   g_rowptr[NN + 1];
__device__ int   g_rowfill[NN];
__device__ int2  g_csr_sw[EE];                      // (src, bitcast weight)
__device__ float g_Wall[FI * KORD * HD2];           // [128][2048] repacked weights
__device__ float g_Y[(size_t)KORD * NN * HD2];      // y_k = x @ W_k
__device__ float g_B[3][NN * HD2];                  // Clenshaw ring buffers
__device__ float g_h[NN * HDIM];
__device__ float g_xp[NN * HDIM];
__device__ float g_asv[NN];
__device__ float g_adv[NN];
__device__ float g_u[NN];
__device__ float g_v[NN];
__device__ float g_p[HDIM];
__device__ float g_q[HDIM];
__device__ float g_cuv[2];

// ---------------- setup kernels ----------------
__global__ void k_zero() {
    int i = blockIdx.x * blockDim.x + threadIdx.x;
    int stride = gridDim.x * blockDim.x;
    for (int t = i; t < NN; t += stride) { g_deg[t] = 0; g_rowcnt[t] = 0; g_rowfill[t] = 0; }
    for (int t = i; t < NN * HD2; t += stride) { g_B[1][t] = 0.f; g_B[2][t] = 0.f; }
}

__global__ void k_hist(const int* __restrict__ ei) {
    int e = blockIdx.x * blockDim.x + threadIdx.x;
    if (e >= EE) return;
    atomicAdd(&g_deg[ei[e]], 1);         // out-degree over src
    atomicAdd(&g_rowcnt[ei[EE + e]], 1); // in-count over dst (CSR rows)
}

// single block: dis + exclusive scan of rowcnt -> rowptr
__global__ void k_scan() {
    __shared__ int ssum[1024];
    int t = threadIdx.x;
    const int CH = 20; // 1024*20 >= 20000
    int base = t * CH;
    int s = 0;
    for (int i = 0; i < CH; i++) { int idx = base + i; if (idx < NN) s += g_rowcnt[idx]; }
    ssum[t] = s; __syncthreads();
    for (int off = 1; off < 1024; off <<= 1) {
        int v = (t >= off) ? ssum[t - off] : 0;
        __syncthreads();
        ssum[t] += v;
        __syncthreads();
    }
    int run = (t > 0) ? ssum[t - 1] : 0;
    for (int i = 0; i < CH; i++) {
        int idx = base + i;
        if (idx < NN) { g_rowptr[idx] = run; run += g_rowcnt[idx]; }
    }
    if (t == 1023) g_rowptr[NN] = EE;
    for (int i = 0; i < CH; i++) {
        int idx = base + i;
        if (idx < NN) {
            int d = g_deg[idx];
            g_dis[idx] = (d > 0) ? rsqrtf((float)d) : 0.f;
        }
    }
}

__global__ void k_scatter(const int* __restrict__ ei) {
    int e = blockIdx.x * blockDim.x + threadIdx.x;
    if (e >= EE) return;
    int s = ei[e], d = ei[EE + e];
    int pos = g_rowptr[d] + atomicAdd(&g_rowfill[d], 1);
    g_csr_sw[pos] = make_int2(s, __float_as_int(-g_dis[s] * g_dis[d]));
}

// repack [K,F,32]+[K,F,32] -> Wall[f][k*64+j]
__global__ void k_prep_wall(const float* __restrict__ Wxz, const float* __restrict__ Wxh) {
    int idx = blockIdx.x * blockDim.x + threadIdx.x;
    if (idx >= FI * KORD * HD2) return;
    int f = idx / (KORD * HD2);
    int c = idx % (KORD * HD2);
    int k = c >> 6;
    int j = c & 63;
    g_Wall[idx] = (j < HDIM) ? Wxz[(k * FI + f) * HDIM + j]
                             : Wxh[(k * FI + f) * HDIM + (j - HDIM)];
}

// p = W_emb @ W_cls[:128], q = W_emb @ W_cls[128:], cuv = b_emb . W_cls halves
__global__ void k_prep_pq(const float* __restrict__ Wemb, const float* __restrict__ bemb,
                          const float* __restrict__ Wcls) {
    int t = threadIdx.x; // 64
    int i = t & 31;
    const float* wc = Wcls + ((t < 32) ? 0 : 128);
    float s = 0.f;
    for (int d = 0; d < 128; d++) s += Wemb[i * 128 + d] * wc[d];
    if (t < 32) g_p[i] = s; else g_q[i] = s;
    if (t < 2) {
        const float* w2 = Wcls + t * 128;
        float c = 0.f;
        for (int d = 0; d < 128; d++) c += bemb[d] * w2[d];
        g_cuv[t] = c;
    }
}

// ---------------- tf32 tensor-core GEMM (3xTF32 split) ----------------
__device__ __forceinline__ float tf32_rna(float v) {
    unsigned r;
    asm("cvt.rna.tf32.f32 %0, %1;" : "=r"(r) : "f"(v));
    return __uint_as_float(r);
}

__device__ __forceinline__ void mma8(float c[4], const float a[4], const float b[2]) {
    const unsigned* A = reinterpret_cast<const unsigned*>(a);
    const unsigned* B = reinterpret_cast<const unsigned*>(b);
    asm volatile("mma.sync.aligned.m16n8k8.row.col.f32.tf32.tf32.f32 "
                 "{%0,%1,%2,%3},{%4,%5,%6,%7},{%8,%9},{%0,%1,%2,%3};"
                 : "+f"(c[0]), "+f"(c[1]), "+f"(c[2]), "+f"(c[3])
                 : "r"(A[0]), "r"(A[1]), "r"(A[2]), "r"(A[3]),
                   "r"(B[0]), "r"(B[1]));
}

#define BM 128
#define BK 16

// Y = x @ Wall : [20000,128] @ [128,2048]; block tile 128x64 (one k-block = blockIdx.y)
__global__ void __launch_bounds__(256) k_gemm(const float* __restrict__ x) {
    __shared__ float xs0[BM][BK + 1], xs1[BM][BK + 1];
    __shared__ float ws0[BK][64 + 1], ws1[BK][64 + 1];
    int n0 = blockIdx.x * BM;
    int cb = blockIdx.y;
    int c0 = cb * 64;
    int tid = threadIdx.x;
    int wid = tid >> 5, lane = tid & 31;
    int m_off = (wid >> 1) * 32;
    int n_off = (wid & 1) * 32;
    float acc[2][4][4];
#pragma unroll
    for (int a = 0; a < 2; a++)
#pragma unroll
        for (int b = 0; b < 4; b++)
#pragma unroll
            for (int c = 0; c < 4; c++) acc[a][b][c] = 0.f;

    for (int kc = 0; kc < FI / BK; kc++) {
        // load x tile: 128 rows x 16 cols = 512 float4
#pragma unroll
        for (int it = 0; it < 2; it++) {
            int id = tid + it * 256;
            int row = id >> 2, q = id & 3;
            int gn = n0 + row;
            float4 v = make_float4(0.f, 0.f, 0.f, 0.f);
            if (gn < NN) v = *(const float4*)(x + (size_t)gn * FI + kc * BK + q * 4);
            float h;
            h = tf32_rna(v.x); xs0[row][q * 4 + 0] = h; xs1[row][q * 4 + 0] = v.x - h;
            h = tf32_rna(v.y); xs0[row][q * 4 + 1] = h; xs1[row][q * 4 + 1] = v.y - h;
            h = tf32_rna(v.z); xs0[row][q * 4 + 2] = h; xs1[row][q * 4 + 2] = v.z - h;
            h = tf32_rna(v.w); xs0[row][q * 4 + 3] = h; xs1[row][q * 4 + 3] = v.w - h;
        }
        // load w tile: 16 rows x 64 cols = 256 float4
        {
            int row = tid >> 4, q = tid & 15;
            float4 v = *(const float4*)(g_Wall + (size_t)(kc * BK + row) * (KORD * HD2) + c0 + q * 4);
            float h;
            h = tf32_rna(v.x); ws0[row][q * 4 + 0] = h; ws1[row][q * 4 + 0] = v.x - h;
            h = tf32_rna(v.y); ws0[row][q * 4 + 1] = h; ws1[row][q * 4 + 1] = v.y - h;
            h = tf32_rna(v.z); ws0[row][q * 4 + 2] = h; ws1[row][q * 4 + 2] = v.z - h;
            h = tf32_rna(v.w); ws0[row][q * 4 + 3] = h; ws1[row][q * 4 + 3] = v.w - h;
        }
        __syncthreads();
#pragma unroll
        for (int k8 = 0; k8 < BK / 8; k8++) {
            float bh[4][2], bl[4][2];
            int kr = (k8 << 3) + (lane & 3);
#pragma unroll
            for (int nf = 0; nf < 4; nf++) {
                int nc = n_off + (nf << 3) + (lane >> 2);
                bh[nf][0] = ws0[kr][nc]; bh[nf][1] = ws0[kr + 4][nc];
                bl[nf][0] = ws1[kr][nc]; bl[nf][1] = ws1[kr + 4][nc];
            }
#pragma unroll
            for (int mf = 0; mf < 2; mf++) {
                int r0 = m_off + (mf << 4) + (lane >> 2);
                int ca = (k8 << 3) + (lane & 3);
                float ah[4] = { xs0[r0][ca], xs0[r0 + 8][ca], xs0[r0][ca + 4], xs0[r0 + 8][ca + 4] };
                float al[4] = { xs1[r0][ca], xs1[r0 + 8][ca], xs1[r0][ca + 4], xs1[r0 + 8][ca + 4] };
#pragma unroll
                for (int nf = 0; nf < 4; nf++) {
                    mma8(acc[mf][nf], ah, bh[nf]);
                    mma8(acc[mf][nf], al, bh[nf]);
                    mma8(acc[mf][nf], ah, bl[nf]);
                }
            }
        }
        __syncthreads();
    }
    // epilogue: Y[(cb*NN + row)*64 + col]
#pragma unroll
    for (int mf = 0; mf < 2; mf++)
#pragma unroll
        for (int nf = 0; nf < 4; nf++) {
            int r = n0 + m_off + (mf << 4) + (lane >> 2);
            int cj = n_off + (nf << 3) + ((lane & 3) << 1);
            if (r < NN)
                *(float2*)(g_Y + ((size_t)cb * NN + r) * HD2 + cj) =
                    make_float2(acc[mf][nf][0], acc[mf][nf][1]);
            if (r + 8 < NN)
                *(float2*)(g_Y + ((size_t)cb * NN + r + 8) * HD2 + cj) =
                    make_float2(acc[mf][nf][2], acc[mf][nf][3]);
        }
}

// ---------------- Clenshaw step: b_new = Y[k] + 2*L*b1 - b2 (warp/node, batched edges)
__global__ void __launch_bounds__(256) k_cheb_step(int k, int ibn, int ib1, int ib2) {
    int gw = blockIdx.x * 8 + (threadIdx.x >> 5);
    int lane = threadIdx.x & 31;
    if (gw >= NN) return;
    const float* __restrict__ yk = g_Y + (size_t)k * NN * HD2;
    const float* __restrict__ b1 = g_B[ib1];
    const float* __restrict__ b2 = g_B[ib2];
    float* __restrict__ bn = g_B[ibn];
    int rs = g_rowptr[gw], re = g_rowptr[gw + 1];
    int j = lane * 2;
    float ax = 0.f, ay = 0.f;
    for (int base = rs; base < re; base += 32) {
        int idx = base + lane;
        int2 sw = (idx < re) ? g_csr_sw[idx] : make_int2(0, 0);
        int n = min(32, re - base);
#pragma unroll 4
        for (int i = 0; i < n; i++) {
            int   si = __shfl_sync(0xffffffffu, sw.x, i);
            float wi = __int_as_float(__shfl_sync(0xffffffffu, sw.y, i));
            float2 v = *(const float2*)(b1 + (size_t)si * HD2 + j);
            ax = fmaf(wi, v.x, ax);
            ay = fmaf(wi, v.y, ay);
        }
    }
    float2 y = *(const float2*)(yk + (size_t)gw * HD2 + j);
    float2 p = *(const float2*)(b2 + (size_t)gw * HD2 + j);
    *(float2*)(bn + (size_t)gw * HD2 + j) =
        make_float2(y.x + 2.f * ax - p.x, y.y + 2.f * ay - p.y);
}

// final: out64 = Y[0] + L*b1 - b2 ; then h = (1-sigmoid(z_pre))*tanh(h_pre)
__global__ void __launch_bounds__(256) k_cheb_final(int ib1, int ib2,
                             const float* __restrict__ bxz, const float* __restrict__ bhz,
                             const float* __restrict__ bxh, const float* __restrict__ bhh) {
    int gw = blockIdx.x * 8 + (threadIdx.x >> 5);
    int lane = threadIdx.x & 31;
    if (gw >= NN) return;
    const float* __restrict__ y0 = g_Y;
    const float* __restrict__ b1 = g_B[ib1];
    const float* __restrict__ b2 = g_B[ib2];
    int rs = g_rowptr[gw], re = g_rowptr[gw + 1];
    int j = lane * 2;
    float ax = 0.f, ay = 0.f;
    for (int base = rs; base < re; base += 32) {
        int idx = base + lane;
        int2 sw = (idx < re) ? g_csr_sw[idx] : make_int2(0, 0);
        int n = min(32, re - base);
#pragma unroll 4
        for (int i = 0; i < n; i++) {
            int   si = __shfl_sync(0xffffffffu, sw.x, i);
            float wi = __int_as_float(__shfl_sync(0xffffffffu, sw.y, i));
            float2 v = *(const float2*)(b1 + (size_t)si * HD2 + j);
            ax = fmaf(wi, v.x, ax);
            ay = fmaf(wi, v.y, ay);
        }
    }
    float2 y = *(const float2*)(y0 + (size_t)gw * HD2 + j);
    float2 p = *(const float2*)(b2 + (size_t)gw * HD2 + j);
    float ox = y.x + ax - p.x;
    float oy = y.y + ay - p.y;
    // lanes 0..15 hold z columns (0..31), 16..31 hold h columns (32..63)
    float px = __shfl_xor_sync(0xffffffffu, ox, 16);
    float py = __shfl_xor_sync(0xffffffffu, oy, 16);
    if (lane < 16) {
        int j0 = lane * 2;
        float z0 = 1.f / (1.f + __expf(-(ox + bxz[j0] + bhz[j0])));
        float z1 = 1.f / (1.f + __expf(-(oy + bxz[j0 + 1] + bhz[j0 + 1])));
        float t0 = tanhf(px + bxh[j0] + bhh[j0]);
        float t1 = tanhf(py + bxh[j0 + 1] + bhh[j0 + 1]);
        float2 hh;
        hh.x = (1.f - z0) * t0;
        hh.y = (1.f - z1) * t1;
        *(float2*)(g_h + (size_t)gw * HDIM + j0) = hh;
    }
}

// ---------------- GAT ----------------
__global__ void __launch_bounds__(256) k_xp(const float* __restrict__ Wg, const float* __restrict__ asrc,
                     const float* __restrict__ adst) {
    int gw = blockIdx.x * 8 + (threadIdx.x >> 5);
    int lane = threadIdx.x & 31;
    if (gw >= NN) return;
    float hv = g_h[(size_t)gw * HDIM + lane];
    float xpv = 0.f;
#pragma unroll
    for (int i = 0; i < 32; i++)
        xpv += __shfl_sync(0xffffffffu, hv, i) * Wg[i * HDIM + lane];
    g_xp[(size_t)gw * HDIM + lane] = xpv;
    float a = xpv * asrc[lane];
    float b = xpv * adst[lane];
#pragma unroll
    for (int off = 16; off; off >>= 1) {
        a += __shfl_xor_sync(0xffffffffu, a, off);
        b += __shfl_xor_sync(0xffffffffu, b, off);
    }
    if (lane == 0) { g_asv[gw] = a; g_adv[gw] = b; }
}

// online-softmax GAT aggregation per dst node, then fold emb+classifier into u,v
__global__ void __launch_bounds__(256) k_gat(const float* __restrict__ bgat) {
    int gw = blockIdx.x * 8 + (threadIdx.x >> 5);
    int lane = threadIdx.x & 31;
    if (gw >= NN) return;
    float advd = g_adv[gw];
    float xpd = g_xp[(size_t)gw * HDIM + lane];
    float es = g_asv[gw] + advd;               // self loop score
    es = es > 0.f ? es : 0.2f * es;
    float m = es, ssum = 1.f, acc = xpd;
    int rs = g_rowptr[gw], re = g_rowptr[gw + 1];
    for (int base = rs; base < re; base += 32) {
        int idx = base + lane;
        int sv = (idx < re) ? g_csr_sw[idx].x : 0;
        int n = min(32, re - base);
        for (int i = 0; i < n; i++) {
            int s = __shfl_sync(0xffffffffu, sv, i);
            float sc = g_asv[s] + advd;
            sc = sc > 0.f ? sc : 0.2f * sc;
            float xv = g_xp[(size_t)s * HDIM + lane];
            float nm = fmaxf(m, sc);
            float r = __expf(m - nm);
            float w = __expf(sc - nm);
            ssum = ssum * r + w;
            acc = acc * r + w * xv;
            m = nm;
        }
    }
    float h2 = acc / ssum + bgat[lane];
    h2 = fmaxf(h2, 0.f);
    float a = h2 * g_p[lane];
    float b = h2 * g_q[lane];
#pragma unroll
    for (int off = 16; off; off >>= 1) {
        a += __shfl_xor_sync(0xffffffffu, a, off);
        b += __shfl_xor_sync(0xffffffffu, b, off);
    }
    if (lane == 0) { g_u[gw] = a + g_cuv[0]; g_v[gw] = b + g_cuv[1]; }
}

__global__ void k_out(const int* __restrict__ ei, const float* __restrict__ bcls,
                      float* __restrict__ out) {
    int e = blockIdx.x * blockDim.x + threadIdx.x;
    if (e >= EE) return;
    out[e] = g_u[ei[e]] + g_v[ei[EE + e]] + bcls[0];
}

// ---------------- launch ----------------
extern "C" void kernel_launch(void* const* d_in, const int* in_sizes, int n_in,
                              void* d_out, int out_size) {
    const float* x    = (const float*)d_in[0];
    const int*   ei   = (const int*)d_in[1];
    const float* Wxz  = (const float*)d_in[2];
    const float* Wxh  = (const float*)d_in[6];
    const float* bxz  = (const float*)d_in[8];
    const float* bhz  = (const float*)d_in[9];
    const float* bxh  = (const float*)d_in[12];
    const float* bhh  = (const float*)d_in[13];
    const float* Wgat = (const float*)d_in[14];
    const float* asrc = (const float*)d_in[15];
    const float* adst = (const float*)d_in[16];
    const float* bgat = (const float*)d_in[17];
    const float* Wemb = (const float*)d_in[18];
    const float* bemb = (const float*)d_in[19];
    const float* Wcls = (const float*)d_in[20];
    const float* bcls = (const float*)d_in[21];
    float* out = (float*)d_out;

    const int EB = (EE + 255) / 256;     // 1250
    const int NB = (NN + 7) / 8;         // 2500 blocks (warp per node, 8 warps/block)

    k_zero<<<256, 256>>>();
    k_hist<<<EB, 256>>>(ei);
    k_scan<<<1, 1024>>>();
    k_scatter<<<EB, 256>>>(ei);
    k_prep_wall<<<(FI * KORD * HD2) / 256, 256>>>(Wxz, Wxh);
    k_prep_pq<<<1, 64>>>(Wemb, bemb, Wcls);
    k_gemm<<<dim3((NN + BM - 1) / BM, KORD), 256>>>(x);

    int bn = 0, b1 = 1, b2 = 2;
    for (int k = KORD - 1; k >= 1; k--) {
        k_cheb_step<<<NB, 256>>>(k, bn, b1, b2);
        int t = b2; b2 = b1; b1 = bn; bn = t;
    }
    k_cheb_final<<<NB, 256>>>(b1, b2, bxz, bhz, bxh, bhh);
    k_xp<<<NB, 256>>>(Wgat, asrc, adst);
    k_gat<<<NB, 256>>>(bgat);
    k_out<<<EB, 256>>>(ei, bcls, out);
}

// round 7
// speedup vs baseline: 1.3632x; 1.3632x over previous
#include <cuda_runtime.h>
#include <cuda_bf16.h>
#include <math.h>

#define NN 20000
#define EE 320000
#define FI 128
#define HDIM 32
#define KORD 32
#define HD2 64

// ---------------- static device scratch ----------------
__device__ int   g_deg[NN];
__device__ float g_dis[NN];
__device__ int   g_rowcnt[NN];
__device__ int   g_rowptr[NN + 1];
__device__ int   g_rowfill[NN];
__device__ int   g_csr_src[EE];
__device__ float g_csr_w[EE];
__device__ __nv_bfloat16 g_Wh[2048 * 128];   // [n][f] K-major, hi part
__device__ __nv_bfloat16 g_Wl[2048 * 128];   // lo residual
__device__ float g_Y[(size_t)KORD * NN * HD2];
__device__ float g_B[3][NN * HD2];
__device__ float g_h[NN * HDIM];
__device__ float g_xp[NN * HDIM];
__device__ float g_asv[NN];
__device__ float g_adv[NN];
__device__ float g_u[NN];
__device__ float g_v[NN];
__device__ float g_p[HDIM];
__device__ float g_q[HDIM];
__device__ float g_cuv[2];

// ---------------- setup kernels (R1-proven) ----------------
__global__ void k_zero() {
    int i = blockIdx.x * blockDim.x + threadIdx.x;
    int stride = gridDim.x * blockDim.x;
    for (int t = i; t < NN; t += stride) { g_deg[t] = 0; g_rowcnt[t] = 0; g_rowfill[t] = 0; }
    for (int t = i; t < NN * HD2; t += stride) { g_B[1][t] = 0.f; g_B[2][t] = 0.f; }
}

__global__ void k_hist(const int* __restrict__ ei) {
    int e = blockIdx.x * blockDim.x + threadIdx.x;
    if (e >= EE) return;
    atomicAdd(&g_deg[ei[e]], 1);
    atomicAdd(&g_rowcnt[ei[EE + e]], 1);
}

__global__ void k_scan() {
    __shared__ int ssum[1024];
    int t = threadIdx.x;
    const int CH = 20;
    int base = t * CH;
    int s = 0;
    for (int i = 0; i < CH; i++) { int idx = base + i; if (idx < NN) s += g_rowcnt[idx]; }
    ssum[t] = s; __syncthreads();
    for (int off = 1; off < 1024; off <<= 1) {
        int v = (t >= off) ? ssum[t - off] : 0;
        __syncthreads();
        ssum[t] += v;
        __syncthreads();
    }
    int run = (t > 0) ? ssum[t - 1] : 0;
    for (int i = 0; i < CH; i++) {
        int idx = base + i;
        if (idx < NN) { g_rowptr[idx] = run; run += g_rowcnt[idx]; }
    }
    if (t == 1023) g_rowptr[NN] = EE;
    for (int i = 0; i < CH; i++) {
        int idx = base + i;
        if (idx < NN) {
            int d = g_deg[idx];
            g_dis[idx] = (d > 0) ? rsqrtf((float)d) : 0.f;
        }
    }
}

__global__ void k_scatter(const int* __restrict__ ei) {
    int e = blockIdx.x * blockDim.x + threadIdx.x;
    if (e >= EE) return;
    int s = ei[e], d = ei[EE + e];
    int pos = g_rowptr[d] + atomicAdd(&g_rowfill[d], 1);
    g_csr_src[pos] = s;
    g_csr_w[pos] = -g_dis[s] * g_dis[d];
}

__global__ void k_prep_wbf(const float* __restrict__ Wxz, const float* __restrict__ Wxh) {
    int idx = blockIdx.x * blockDim.x + threadIdx.x;
    if (idx >= 2048 * 128) return;
    int n = idx >> 7, f = idx & 127;
    int k = n >> 6, j = n & 63;
    float w = (j < HDIM) ? Wxz[(k * FI + f) * HDIM + j]
                         : Wxh[(k * FI + f) * HDIM + (j - HDIM)];
    __nv_bfloat16 h = __float2bfloat16(w);
    g_Wh[idx] = h;
    g_Wl[idx] = __float2bfloat16(w - __bfloat162float(h));
}

__global__ void k_prep_pq(const float* __restrict__ Wemb, const float* __restrict__ bemb,
                          const float* __restrict__ Wcls) {
    int t = threadIdx.x;
    int i = t & 31;
    const float* wc = Wcls + ((t < 32) ? 0 : 128);
    float s = 0.f;
    for (int d = 0; d < 128; d++) s += Wemb[i * 128 + d] * wc[d];
    if (t < 32) g_p[i] = s; else g_q[i] = s;
    if (t < 2) {
        const float* w2 = Wcls + t * 128;
        float c = 0.f;
        for (int d = 0; d < 128; d++) c += bemb[d] * w2[d];
        g_cuv[t] = c;
    }
}

// ---------------- bf16 mma.sync GEMM with ldmatrix ----------------
__device__ __forceinline__ unsigned smem_u32(const void* p) {
    unsigned a;
    asm("{ .reg .u64 t; cvta.to.shared.u64 t, %1; cvt.u32.u64 %0, t; }" : "=r"(a) : "l"(p));
    return a;
}

__device__ __forceinline__ void ldsm4(unsigned* r, unsigned addr) {
    asm volatile("ldmatrix.sync.aligned.m8n8.x4.shared.b16 {%0,%1,%2,%3}, [%4];"
        : "=r"(r[0]), "=r"(r[1]), "=r"(r[2]), "=r"(r[3]) : "r"(addr));
}

__device__ __forceinline__ void mma16(float* c, const unsigned* a, unsigned b0, unsigned b1) {
    asm volatile("mma.sync.aligned.m16n8k16.row.col.f32.bf16.bf16.f32 "
        "{%0,%1,%2,%3},{%4,%5,%6,%7},{%8,%9},{%0,%1,%2,%3};"
        : "+f"(c[0]), "+f"(c[1]), "+f"(c[2]), "+f"(c[3])
        : "r"(a[0]), "r"(a[1]), "r"(a[2]), "r"(a[3]), "r"(b0), "r"(b1));
}

__device__ __forceinline__ void split8(float4 v0, float4 v1, uint4* hi, uint4* lo) {
    float f[8];
    f[0] = v0.x; f[1] = v0.y; f[2] = v0.z; f[3] = v0.w;
    f[4] = v1.x; f[5] = v1.y; f[6] = v1.z; f[7] = v1.w;
    unsigned h[4], l[4];
#pragma unroll
    for (int i = 0; i < 4; i++) {
        float a = f[2 * i], b = f[2 * i + 1];
        __nv_bfloat16 ha = __float2bfloat16(a), hb = __float2bfloat16(b);
        float ra = a - __bfloat162float(ha), rb = b - __bfloat162float(hb);
        __nv_bfloat16 la = __float2bfloat16(ra), lb = __float2bfloat16(rb);
        h[i] = (unsigned)__bfloat16_as_ushort(ha) | ((unsigned)__bfloat16_as_ushort(hb) << 16);
        l[i] = (unsigned)__bfloat16_as_ushort(la) | ((unsigned)__bfloat16_as_ushort(lb) << 16);
    }
    *hi = make_uint4(h[0], h[1], h[2], h[3]);
    *lo = make_uint4(l[0], l[1], l[2], l[3]);
}

// grid (157, 32); block 256 (8 warps, warp tile 32x32); tile M=128, N=64, K=128 in 2 chunks of 64
__global__ void __launch_bounds__(256) k_gemm(const float* __restrict__ x) {
    // each tile row = 64 bf16 = 128B = 8 units of 16B; unit swizzled by (row & 7)
    __shared__ __align__(16) unsigned char sAh[16384], sAl[16384];  // 128 x 128B
    __shared__ __align__(16) unsigned char sBh[8192],  sBl[8192];   // 64 x 128B
    unsigned bAh = smem_u32(sAh), bAl = smem_u32(sAl);
    unsigned bBh = smem_u32(sBh), bBl = smem_u32(sBl);

    int tid = threadIdx.x, wid = tid >> 5, lane = tid & 31;
    int n0 = blockIdx.x * 128;       // row tile base
    int cb = blockIdx.y;             // 64-col block index (0..31)
    int m_w = (wid >> 1) * 32;       // warp m offset (0,32,64,96)
    int n_w = (wid & 1) * 32;        // warp n offset (0,32)

    float acc[2][4][4];
#pragma unroll
    for (int a = 0; a < 2; a++)
#pragma unroll
        for (int b = 0; b < 4; b++)
#pragma unroll
            for (int c = 0; c < 4; c++) acc[a][b][c] = 0.f;

    for (int kc = 0; kc < 2; kc++) {
        if (kc) __syncthreads();
        // A tile: rows n0..n0+127, cols kc*64..+63 -> bf16 hi/lo
        {
            int r = tid >> 1, h = tid & 1;
            int gr = n0 + r;
#pragma unroll
            for (int i = 0; i < 4; i++) {
                float4 v0 = make_float4(0.f, 0.f, 0.f, 0.f), v1 = v0;
                if (gr < NN) {
                    const float4* xr = (const float4*)(x + (size_t)gr * FI + kc * 64 + h * 32);
                    v0 = xr[2 * i];
                    v1 = xr[2 * i + 1];
                }
                uint4 hi, lo;
                split8(v0, v1, &hi, &lo);
                int c = h * 4 + i;
                unsigned off = (unsigned)(r * 128 + ((c ^ (r & 7)) << 4));
                *(uint4*)(sAh + off) = hi;
                *(uint4*)(sAl + off) = lo;
            }
        }
        // B tile: weight rows cb*64..+63, cols kc*64..+63 (already bf16 hi/lo in gmem)
        {
            int nr = tid >> 2, q = tid & 3;
            size_t src = (size_t)(cb * 64 + nr) * 128 + kc * 64;
#pragma unroll
            for (int i = 0; i < 2; i++) {
                int c = q * 2 + i;
                uint4 hv = *(const uint4*)(g_Wh + src + c * 8);
                uint4 lv = *(const uint4*)(g_Wl + src + c * 8);
                unsigned off = (unsigned)(nr * 128 + ((c ^ (nr & 7)) << 4));
                *(uint4*)(sBh + off) = hv;
                *(uint4*)(sBl + off) = lv;
            }
        }
        __syncthreads();

#pragma unroll
        for (int s = 0; s < 4; s++) {
            int c0 = s * 2;
            unsigned ah[2][4], al[2][4], bh[2][4], bl[2][4];
#pragma unroll
            for (int mt = 0; mt < 2; mt++) {
                int rr = m_w + mt * 16 + (lane & 15);
                int c = c0 + (lane >> 4);
                unsigned off = (unsigned)(rr * 128 + ((c ^ (rr & 7)) << 4));
                ldsm4(ah[mt], bAh + off);
                ldsm4(al[mt], bAl + off);
            }
#pragma unroll
            for (int ng = 0; ng < 2; ng++) {
                int nr = n_w + ng * 16 + (lane & 15);
                int c = c0 + (lane >> 4);
                unsigned off = (unsigned)(nr * 128 + ((c ^ (nr & 7)) << 4));
                ldsm4(bh[ng], bBh + off);
                ldsm4(bl[ng], bBl + off);
            }
#pragma unroll
            for (int mt = 0; mt < 2; mt++)
#pragma unroll
                for (int ng = 0; ng < 2; ng++)
#pragma unroll
                    for (int hf = 0; hf < 2; hf++) {
                        float* c = acc[mt][ng * 2 + hf];
                        mma16(c, ah[mt], bh[ng][hf], bh[ng][2 + hf]);
                        mma16(c, al[mt], bh[ng][hf], bh[ng][2 + hf]);
                        mma16(c, ah[mt], bl[ng][hf], bl[ng][2 + hf]);
                    }
        }
    }

    // epilogue
#pragma unroll
    for (int mt = 0; mt < 2; mt++)
#pragma unroll
        for (int ng = 0; ng < 2; ng++)
#pragma unroll
            for (int hf = 0; hf < 2; hf++) {
                float* c = acc[mt][ng * 2 + hf];
                int m0 = n0 + m_w + mt * 16 + (lane >> 2);
                int col = n_w + ng * 16 + hf * 8 + (lane & 3) * 2;
                if (m0 < NN)
                    *(float2*)(g_Y + ((size_t)cb * NN + m0) * HD2 + col) = make_float2(c[0], c[1]);
                if (m0 + 8 < NN)
                    *(float2*)(g_Y + ((size_t)cb * NN + m0 + 8) * HD2 + col) = make_float2(c[2], c[3]);
            }
}

// ---------------- Clenshaw step (R1-proven) ----------------
__global__ void k_cheb_step(int k, int ibn, int ib1, int ib2) {
    int gw = (blockIdx.x * blockDim.x + threadIdx.x) >> 5;
    int lane = threadIdx.x & 31;
    if (gw >= NN) return;
    const float* yk = g_Y + (size_t)k * NN * HD2;
    const float* b1 = g_B[ib1];
    const float* b2 = g_B[ib2];
    float* bn = g_B[ibn];
    int rs = g_rowptr[gw], re = g_rowptr[gw + 1];
    int j = lane * 2;
    float ax = 0.f, ay = 0.f;
    for (int e = rs; e < re; e++) {
        int s = g_csr_src[e];
        float w = g_csr_w[e];
        float2 v = *(const float2*)(b1 + (size_t)s * HD2 + j);
        ax += w * v.x; ay += w * v.y;
    }
    float2 y = *(const float2*)(yk + (size_t)gw * HD2 + j);
    float2 p = *(const float2*)(b2 + (size_t)gw * HD2 + j);
    float2 o;
    o.x = y.x + 2.f * ax - p.x;
    o.y = y.y + 2.f * ay - p.y;
    *(float2*)(bn + (size_t)gw * HD2 + j) = o;
}

__global__ void k_cheb_final(int ib1, int ib2,
                             const float* __restrict__ bxz, const float* __restrict__ bhz,
                             const float* __restrict__ bxh, const float* __restrict__ bhh) {
    int gw = (blockIdx.x * blockDim.x + threadIdx.x) >> 5;
    int lane = threadIdx.x & 31;
    if (gw >= NN) return;
    const float* y0 = g_Y;
    const float* b1 = g_B[ib1];
    const float* b2 = g_B[ib2];
    int rs = g_rowptr[gw], re = g_rowptr[gw + 1];
    int j = lane * 2;
    float ax = 0.f, ay = 0.f;
    for (int e = rs; e < re; e++) {
        int s = g_csr_src[e];
        float w = g_csr_w[e];
        float2 v = *(const float2*)(b1 + (size_t)s * HD2 + j);
        ax += w * v.x; ay += w * v.y;
    }
    float2 y = *(const float2*)(y0 + (size_t)gw * HD2 + j);
    float2 p = *(const float2*)(b2 + (size_t)gw * HD2 + j);
    float ox = y.x + ax - p.x;
    float oy = y.y + ay - p.y;
    float px = __shfl_xor_sync(0xffffffffu, ox, 16);
    float py = __shfl_xor_sync(0xffffffffu, oy, 16);
    if (lane < 16) {
        int j0 = lane * 2;
        float z0 = 1.f / (1.f + __expf(-(ox + bxz[j0] + bhz[j0])));
        float z1 = 1.f / (1.f + __expf(-(oy + bxz[j0 + 1] + bhz[j0 + 1])));
        float t0 = tanhf(px + bxh[j0] + bhh[j0]);
        float t1 = tanhf(py + bxh[j0 + 1] + bhh[j0 + 1]);
        float2 hh;
        hh.x = (1.f - z0) * t0;
        hh.y = (1.f - z1) * t1;
        *(float2*)(g_h + (size_t)gw * HDIM + j0) = hh;
    }
}

// ---------------- GAT (R1-proven) ----------------
__global__ void k_xp(const float* __restrict__ Wg, const float* __restrict__ asrc,
                     const float* __restrict__ adst) {
    int gw = (blockIdx.x * blockDim.x + threadIdx.x) >> 5;
    int lane = threadIdx.x & 31;
    if (gw >= NN) return;
    float hv = g_h[(size_t)gw * HDIM + lane];
    float xpv = 0.f;
#pragma unroll
    for (int i = 0; i < 32; i++)
        xpv += __shfl_sync(0xffffffffu, hv, i) * Wg[i * HDIM + lane];
    g_xp[(size_t)gw * HDIM + lane] = xpv;
    float a = xpv * asrc[lane];
    float b = xpv * adst[lane];
#pragma unroll
    for (int off = 16; off; off >>= 1) {
        a += __shfl_xor_sync(0xffffffffu, a, off);
        b += __shfl_xor_sync(0xffffffffu, b, off);
    }
    if (lane == 0) { g_asv[gw] = a; g_adv[gw] = b; }
}

__global__ void k_gat(const float* __restrict__ bgat) {
    int gw = (blockIdx.x * blockDim.x + threadIdx.x) >> 5;
    int lane = threadIdx.x & 31;
    if (gw >= NN) return;
    float advd = g_adv[gw];
    float xpd = g_xp[(size_t)gw * HDIM + lane];
    float es = g_asv[gw] + advd;
    es = es > 0.f ? es : 0.2f * es;
    float m = es, ssum = 1.f, acc = xpd;
    int rs = g_rowptr[gw], re = g_rowptr[gw + 1];
    for (int e = rs; e < re; e++) {
        int s = g_csr_src[e];
        float sc = g_asv[s] + advd;
        sc = sc > 0.f ? sc : 0.2f * sc;
        float xv = g_xp[(size_t)s * HDIM + lane];
        float nm = fmaxf(m, sc);
        float r = __expf(m - nm);
        float w = __expf(sc - nm);
        ssum = ssum * r + w;
        acc = acc * r + w * xv;
        m = nm;
    }
    float h2 = acc / ssum + bgat[lane];
    h2 = fmaxf(h2, 0.f);
    float a = h2 * g_p[lane];
    float b = h2 * g_q[lane];
#pragma unroll
    for (int off = 16; off; off >>= 1) {
        a += __shfl_xor_sync(0xffffffffu, a, off);
        b += __shfl_xor_sync(0xffffffffu, b, off);
    }
    if (lane == 0) { g_u[gw] = a + g_cuv[0]; g_v[gw] = b + g_cuv[1]; }
}

__global__ void k_out(const int* __restrict__ ei, const float* __restrict__ bcls,
                      float* __restrict__ out) {
    int e = blockIdx.x * blockDim.x + threadIdx.x;
    if (e >= EE) return;
    out[e] = g_u[ei[e]] + g_v[ei[EE + e]] + bcls[0];
}

// ---------------- launch ----------------
extern "C" void kernel_launch(void* const* d_in, const int* in_sizes, int n_in,
                              void* d_out, int out_size) {
    const float* x    = (const float*)d_in[0];
    const int*   ei   = (const int*)d_in[1];
    const float* Wxz  = (const float*)d_in[2];
    const float* Wxh  = (const float*)d_in[6];
    const float* bxz  = (const float*)d_in[8];
    const float* bhz  = (const float*)d_in[9];
    const float* bxh  = (const float*)d_in[12];
    const float* bhh  = (const float*)d_in[13];
    const float* Wgat = (const float*)d_in[14];
    const float* asrc = (const float*)d_in[15];
    const float* adst = (const float*)d_in[16];
    const float* bgat = (const float*)d_in[17];
    const float* Wemb = (const float*)d_in[18];
    const float* bemb = (const float*)d_in[19];
    const float* Wcls = (const float*)d_in[20];
    const float* bcls = (const float*)d_in[21];
    float* out = (float*)d_out;

    const int EB = (EE + 255) / 256;
    const int NB = (NN * 32 + 255) / 256;

    // order chosen so k_gemm is our 4th launch (the one ncu captures)
    k_zero<<<256, 256>>>();
    k_hist<<<EB, 256>>>(ei);
    k_prep_wbf<<<1024, 256>>>(Wxz, Wxh);
    k_gemm<<<dim3(157, 32), 256>>>(x);
    k_scan<<<1, 1024>>>();
    k_scatter<<<EB, 256>>>(ei);
    k_prep_pq<<<1, 64>>>(Wemb, bemb, Wcls);

    int bn = 0, b1 = 1, b2 = 2;
    for (int k = KORD - 1; k >= 1; k--) {
        k_cheb_step<<<NB, 256>>>(k, bn, b1, b2);
        int t = b2; b2 = b1; b1 = bn; bn = t;
    }
    k_cheb_final<<<NB, 256>>>(b1, b2, bxz, bhz, bxh, bhh);
    k_xp<<<NB, 256>>>(Wgat, asrc, adst);
    k_gat<<<NB, 256>>>(bgat);
    k_out<<<EB, 256>>>(ei, bcls, out);
}

// round 8
// speedup vs baseline: 1.4485x; 1.0626x over previous
#include <cuda_runtime.h>
#include <cuda_bf16.h>
#include <math.h>

#define NN 20000
#define EE 320000
#define FI 128
#define HDIM 32
#define KORD 32
#define HD2 64

// ---------------- static device scratch ----------------
__device__ int   g_deg[NN];
__device__ float g_dis[NN];
__device__ int   g_rowcnt[NN];
__device__ int   g_rowptr[NN + 1];
__device__ int   g_rowfill[NN];
__device__ int   g_csr_src[EE];
__device__ float g_csr_w[EE];
__device__ __nv_bfloat16 g_Wh[2048 * 128];   // [n][f] K-major, hi part
__device__ __nv_bfloat16 g_Wl[2048 * 128];   // lo residual
__device__ float g_Y[(size_t)KORD * NN * HD2];
__device__ float g_B[3][NN * HD2];
__device__ float g_h[NN * HDIM];
__device__ float g_xp[NN * HDIM];
__device__ float g_asv[NN];
__device__ float g_adv[NN];
__device__ float g_u[NN];
__device__ float g_v[NN];
__device__ float g_p[HDIM];
__device__ float g_q[HDIM];
__device__ float g_cuv[2];

// ---------------- setup kernels (R1-proven) ----------------
__global__ void k_zero() {
    int i = blockIdx.x * blockDim.x + threadIdx.x;
    int stride = gridDim.x * blockDim.x;
    for (int t = i; t < NN; t += stride) { g_deg[t] = 0; g_rowcnt[t] = 0; g_rowfill[t] = 0; }
    for (int t = i; t < NN * HD2; t += stride) { g_B[1][t] = 0.f; g_B[2][t] = 0.f; }
}

__global__ void k_hist(const int* __restrict__ ei) {
    int e = blockIdx.x * blockDim.x + threadIdx.x;
    if (e >= EE) return;
    atomicAdd(&g_deg[ei[e]], 1);
    atomicAdd(&g_rowcnt[ei[EE + e]], 1);
}

__global__ void k_scan() {
    __shared__ int ssum[1024];
    int t = threadIdx.x;
    const int CH = 20;
    int base = t * CH;
    int s = 0;
    for (int i = 0; i < CH; i++) { int idx = base + i; if (idx < NN) s += g_rowcnt[idx]; }
    ssum[t] = s; __syncthreads();
    for (int off = 1; off < 1024; off <<= 1) {
        int v = (t >= off) ? ssum[t - off] : 0;
        __syncthreads();
        ssum[t] += v;
        __syncthreads();
    }
    int run = (t > 0) ? ssum[t - 1] : 0;
    for (int i = 0; i < CH; i++) {
        int idx = base + i;
        if (idx < NN) { g_rowptr[idx] = run; run += g_rowcnt[idx]; }
    }
    if (t == 1023) g_rowptr[NN] = EE;
    for (int i = 0; i < CH; i++) {
        int idx = base + i;
        if (idx < NN) {
            int d = g_deg[idx];
            g_dis[idx] = (d > 0) ? rsqrtf((float)d) : 0.f;
        }
    }
}

__global__ void k_scatter(const int* __restrict__ ei) {
    int e = blockIdx.x * blockDim.x + threadIdx.x;
    if (e >= EE) return;
    int s = ei[e], d = ei[EE + e];
    int pos = g_rowptr[d] + atomicAdd(&g_rowfill[d], 1);
    g_csr_src[pos] = s;
    g_csr_w[pos] = -g_dis[s] * g_dis[d];
}

__global__ void k_prep_wbf(const float* __restrict__ Wxz, const float* __restrict__ Wxh) {
    int idx = blockIdx.x * blockDim.x + threadIdx.x;
    if (idx >= 2048 * 128) return;
    int n = idx >> 7, f = idx & 127;
    int k = n >> 6, j = n & 63;
    float w = (j < HDIM) ? Wxz[(k * FI + f) * HDIM + j]
                         : Wxh[(k * FI + f) * HDIM + (j - HDIM)];
    __nv_bfloat16 h = __float2bfloat16(w);
    g_Wh[idx] = h;
    g_Wl[idx] = __float2bfloat16(w - __bfloat162float(h));
}

__global__ void k_prep_pq(const float* __restrict__ Wemb, const float* __restrict__ bemb,
                          const float* __restrict__ Wcls) {
    int t = threadIdx.x;
    int i = t & 31;
    const float* wc = Wcls + ((t < 32) ? 0 : 128);
    float s = 0.f;
    for (int d = 0; d < 128; d++) s += Wemb[i * 128 + d] * wc[d];
    if (t < 32) g_p[i] = s; else g_q[i] = s;
    if (t < 2) {
        const float* w2 = Wcls + t * 128;
        float c = 0.f;
        for (int d = 0; d < 128; d++) c += bemb[d] * w2[d];
        g_cuv[t] = c;
    }
}

// ---------------- bf16 mma.sync GEMM with ldmatrix (R7-proven) ----------------
__device__ __forceinline__ unsigned smem_u32(const void* p) {
    unsigned a;
    asm("{ .reg .u64 t; cvta.to.shared.u64 t, %1; cvt.u32.u64 %0, t; }" : "=r"(a) : "l"(p));
    return a;
}

__device__ __forceinline__ void ldsm4(unsigned* r, unsigned addr) {
    asm volatile("ldmatrix.sync.aligned.m8n8.x4.shared.b16 {%0,%1,%2,%3}, [%4];"
        : "=r"(r[0]), "=r"(r[1]), "=r"(r[2]), "=r"(r[3]) : "r"(addr));
}

__device__ __forceinline__ void mma16(float* c, const unsigned* a, unsigned b0, unsigned b1) {
    asm volatile("mma.sync.aligned.m16n8k16.row.col.f32.bf16.bf16.f32 "
        "{%0,%1,%2,%3},{%4,%5,%6,%7},{%8,%9},{%0,%1,%2,%3};"
        : "+f"(c[0]), "+f"(c[1]), "+f"(c[2]), "+f"(c[3])
        : "r"(a[0]), "r"(a[1]), "r"(a[2]), "r"(a[3]), "r"(b0), "r"(b1));
}

__device__ __forceinline__ void split8(float4 v0, float4 v1, uint4* hi, uint4* lo) {
    float f[8];
    f[0] = v0.x; f[1] = v0.y; f[2] = v0.z; f[3] = v0.w;
    f[4] = v1.x; f[5] = v1.y; f[6] = v1.z; f[7] = v1.w;
    unsigned h[4], l[4];
#pragma unroll
    for (int i = 0; i < 4; i++) {
        float a = f[2 * i], b = f[2 * i + 1];
        __nv_bfloat16 ha = __float2bfloat16(a), hb = __float2bfloat16(b);
        float ra = a - __bfloat162float(ha), rb = b - __bfloat162float(hb);
        __nv_bfloat16 la = __float2bfloat16(ra), lb = __float2bfloat16(rb);
        h[i] = (unsigned)__bfloat16_as_ushort(ha) | ((unsigned)__bfloat16_as_ushort(hb) << 16);
        l[i] = (unsigned)__bfloat16_as_ushort(la) | ((unsigned)__bfloat16_as_ushort(lb) << 16);
    }
    *hi = make_uint4(h[0], h[1], h[2], h[3]);
    *lo = make_uint4(l[0], l[1], l[2], l[3]);
}

// grid (157, 8) per chunk; cb = cb_base + blockIdx.y
__global__ void __launch_bounds__(256) k_gemm(const float* __restrict__ x, int cb_base) {
    __shared__ __align__(16) unsigned char sAh[16384], sAl[16384];
    __shared__ __align__(16) unsigned char sBh[8192],  sBl[8192];
    unsigned bAh = smem_u32(sAh), bAl = smem_u32(sAl);
    unsigned bBh = smem_u32(sBh), bBl = smem_u32(sBl);

    int tid = threadIdx.x, wid = tid >> 5, lane = tid & 31;
    int n0 = blockIdx.x * 128;
    int cb = cb_base + blockIdx.y;
    int m_w = (wid >> 1) * 32;
    int n_w = (wid & 1) * 32;

    float acc[2][4][4];
#pragma unroll
    for (int a = 0; a < 2; a++)
#pragma unroll
        for (int b = 0; b < 4; b++)
#pragma unroll
            for (int c = 0; c < 4; c++) acc[a][b][c] = 0.f;

    for (int kc = 0; kc < 2; kc++) {
        if (kc) __syncthreads();
        {
            int r = tid >> 1, h = tid & 1;
            int gr = n0 + r;
#pragma unroll
            for (int i = 0; i < 4; i++) {
                float4 v0 = make_float4(0.f, 0.f, 0.f, 0.f), v1 = v0;
                if (gr < NN) {
                    const float4* xr = (const float4*)(x + (size_t)gr * FI + kc * 64 + h * 32);
                    v0 = xr[2 * i];
                    v1 = xr[2 * i + 1];
                }
                uint4 hi, lo;
                split8(v0, v1, &hi, &lo);
                int c = h * 4 + i;
                unsigned off = (unsigned)(r * 128 + ((c ^ (r & 7)) << 4));
                *(uint4*)(sAh + off) = hi;
                *(uint4*)(sAl + off) = lo;
            }
        }
        {
            int nr = tid >> 2, q = tid & 3;
            size_t src = (size_t)(cb * 64 + nr) * 128 + kc * 64;
#pragma unroll
            for (int i = 0; i < 2; i++) {
                int c = q * 2 + i;
                uint4 hv = *(const uint4*)(g_Wh + src + c * 8);
                uint4 lv = *(const uint4*)(g_Wl + src + c * 8);
                unsigned off = (unsigned)(nr * 128 + ((c ^ (nr & 7)) << 4));
                *(uint4*)(sBh + off) = hv;
                *(uint4*)(sBl + off) = lv;
            }
        }
        __syncthreads();

#pragma unroll
        for (int s = 0; s < 4; s++) {
            int c0 = s * 2;
            unsigned ah[2][4], al[2][4], bh[2][4], bl[2][4];
#pragma unroll
            for (int mt = 0; mt < 2; mt++) {
                int rr = m_w + mt * 16 + (lane & 15);
                int c = c0 + (lane >> 4);
                unsigned off = (unsigned)(rr * 128 + ((c ^ (rr & 7)) << 4));
                ldsm4(ah[mt], bAh + off);
                ldsm4(al[mt], bAl + off);
            }
#pragma unroll
            for (int ng = 0; ng < 2; ng++) {
                int nr = n_w + ng * 16 + (lane & 15);
                int c = c0 + (lane >> 4);
                unsigned off = (unsigned)(nr * 128 + ((c ^ (nr & 7)) << 4));
                ldsm4(bh[ng], bBh + off);
                ldsm4(bl[ng], bBl + off);
            }
#pragma unroll
            for (int mt = 0; mt < 2; mt++)
#pragma unroll
                for (int ng = 0; ng < 2; ng++)
#pragma unroll
                    for (int hf = 0; hf < 2; hf++) {
                        float* c = acc[mt][ng * 2 + hf];
                        mma16(c, ah[mt], bh[ng][hf], bh[ng][2 + hf]);
                        mma16(c, al[mt], bh[ng][hf], bh[ng][2 + hf]);
                        mma16(c, ah[mt], bl[ng][hf], bl[ng][2 + hf]);
                    }
        }
    }

#pragma unroll
    for (int mt = 0; mt < 2; mt++)
#pragma unroll
        for (int ng = 0; ng < 2; ng++)
#pragma unroll
            for (int hf = 0; hf < 2; hf++) {
                float* c = acc[mt][ng * 2 + hf];
                int m0 = n0 + m_w + mt * 16 + (lane >> 2);
                int col = n_w + ng * 16 + hf * 8 + (lane & 3) * 2;
                if (m0 < NN)
                    *(float2*)(g_Y + ((size_t)cb * NN + m0) * HD2 + col) = make_float2(c[0], c[1]);
                if (m0 + 8 < NN)
                    *(float2*)(g_Y + ((size_t)cb * NN + m0 + 8) * HD2 + col) = make_float2(c[2], c[3]);
            }
}

// ---------------- Clenshaw step (R1-proven) ----------------
__global__ void k_cheb_step(int k, int ibn, int ib1, int ib2) {
    int gw = (blockIdx.x * blockDim.x + threadIdx.x) >> 5;
    int lane = threadIdx.x & 31;
    if (gw >= NN) return;
    const float* yk = g_Y + (size_t)k * NN * HD2;
    const float* b1 = g_B[ib1];
    const float* b2 = g_B[ib2];
    float* bn = g_B[ibn];
    int rs = g_rowptr[gw], re = g_rowptr[gw + 1];
    int j = lane * 2;
    float ax = 0.f, ay = 0.f;
    for (int e = rs; e < re; e++) {
        int s = g_csr_src[e];
        float w = g_csr_w[e];
        float2 v = *(const float2*)(b1 + (size_t)s * HD2 + j);
        ax += w * v.x; ay += w * v.y;
    }
    float2 y = *(const float2*)(yk + (size_t)gw * HD2 + j);
    float2 p = *(const float2*)(b2 + (size_t)gw * HD2 + j);
    float2 o;
    o.x = y.x + 2.f * ax - p.x;
    o.y = y.y + 2.f * ay - p.y;
    *(float2*)(bn + (size_t)gw * HD2 + j) = o;
}

__global__ void k_cheb_final(int ib1, int ib2,
                             const float* __restrict__ bxz, const float* __restrict__ bhz,
                             const float* __restrict__ bxh, const float* __restrict__ bhh) {
    int gw = (blockIdx.x * blockDim.x + threadIdx.x) >> 5;
    int lane = threadIdx.x & 31;
    if (gw >= NN) return;
    const float* y0 = g_Y;
    const float* b1 = g_B[ib1];
    const float* b2 = g_B[ib2];
    int rs = g_rowptr[gw], re = g_rowptr[gw + 1];
    int j = lane * 2;
    float ax = 0.f, ay = 0.f;
    for (int e = rs; e < re; e++) {
        int s = g_csr_src[e];
        float w = g_csr_w[e];
        float2 v = *(const float2*)(b1 + (size_t)s * HD2 + j);
        ax += w * v.x; ay += w * v.y;
    }
    float2 y = *(const float2*)(y0 + (size_t)gw * HD2 + j);
    float2 p = *(const float2*)(b2 + (size_t)gw * HD2 + j);
    float ox = y.x + ax - p.x;
    float oy = y.y + ay - p.y;
    float px = __shfl_xor_sync(0xffffffffu, ox, 16);
    float py = __shfl_xor_sync(0xffffffffu, oy, 16);
    if (lane < 16) {
        int j0 = lane * 2;
        float z0 = 1.f / (1.f + __expf(-(ox + bxz[j0] + bhz[j0])));
        float z1 = 1.f / (1.f + __expf(-(oy + bxz[j0 + 1] + bhz[j0 + 1])));
        float t0 = tanhf(px + bxh[j0] + bhh[j0]);
        float t1 = tanhf(py + bxh[j0 + 1] + bhh[j0 + 1]);
        float2 hh;
        hh.x = (1.f - z0) * t0;
        hh.y = (1.f - z1) * t1;
        *(float2*)(g_h + (size_t)gw * HDIM + j0) = hh;
    }
}

// ---------------- GAT (R1-proven) ----------------
__global__ void k_xp(const float* __restrict__ Wg, const float* __restrict__ asrc,
                     const float* __restrict__ adst) {
    int gw = (blockIdx.x * blockDim.x + threadIdx.x) >> 5;
    int lane = threadIdx.x & 31;
    if (gw >= NN) return;
    float hv = g_h[(size_t)gw * HDIM + lane];
    float xpv = 0.f;
#pragma unroll
    for (int i = 0; i < 32; i++)
        xpv += __shfl_sync(0xffffffffu, hv, i) * Wg[i * HDIM + lane];
    g_xp[(size_t)gw * HDIM + lane] = xpv;
    float a = xpv * asrc[lane];
    float b = xpv * adst[lane];
#pragma unroll
    for (int off = 16; off; off >>= 1) {
        a += __shfl_xor_sync(0xffffffffu, a, off);
        b += __shfl_xor_sync(0xffffffffu, b, off);
    }
    if (lane == 0) { g_asv[gw] = a; g_adv[gw] = b; }
}

__global__ void k_gat(const float* __restrict__ bgat) {
    int gw = (blockIdx.x * blockDim.x + threadIdx.x) >> 5;
    int lane = threadIdx.x & 31;
    if (gw >= NN) return;
    float advd = g_adv[gw];
    float xpd = g_xp[(size_t)gw * HDIM + lane];
    float es = g_asv[gw] + advd;
    es = es > 0.f ? es : 0.2f * es;
    float m = es, ssum = 1.f, acc = xpd;
    int rs = g_rowptr[gw], re = g_rowptr[gw + 1];
    for (int e = rs; e < re; e++) {
        int s = g_csr_src[e];
        float sc = g_asv[s] + advd;
        sc = sc > 0.f ? sc : 0.2f * sc;
        float xv = g_xp[(size_t)s * HDIM + lane];
        float nm = fmaxf(m, sc);
        float r = __expf(m - nm);
        float w = __expf(sc - nm);
        ssum = ssum * r + w;
        acc = acc * r + w * xv;
        m = nm;
    }
    float h2 = acc / ssum + bgat[lane];
    h2 = fmaxf(h2, 0.f);
    float a = h2 * g_p[lane];
    float b = h2 * g_q[lane];
#pragma unroll
    for (int off = 16; off; off >>= 1) {
        a += __shfl_xor_sync(0xffffffffu, a, off);
        b += __shfl_xor_sync(0xffffffffu, b, off);
    }
    if (lane == 0) { g_u[gw] = a + g_cuv[0]; g_v[gw] = b + g_cuv[1]; }
}

__global__ void k_out(const int* __restrict__ ei, const float* __restrict__ bcls,
                      float* __restrict__ out) {
    int e = blockIdx.x * blockDim.x + threadIdx.x;
    if (e >= EE) return;
    out[e] = g_u[ei[e]] + g_v[ei[EE + e]] + bcls[0];
}

// ---------------- launch (GEMM overlapped on a second stream) ----------------
extern "C" void kernel_launch(void* const* d_in, const int* in_sizes, int n_in,
                              void* d_out, int out_size) {
    const float* x    = (const float*)d_in[0];
    const int*   ei   = (const int*)d_in[1];
    const float* Wxz  = (const float*)d_in[2];
    const float* Wxh  = (const float*)d_in[6];
    const float* bxz  = (const float*)d_in[8];
    const float* bhz  = (const float*)d_in[9];
    const float* bxh  = (const float*)d_in[12];
    const float* bhh  = (const float*)d_in[13];
    const float* Wgat = (const float*)d_in[14];
    const float* asrc = (const float*)d_in[15];
    const float* adst = (const float*)d_in[16];
    const float* bgat = (const float*)d_in[17];
    const float* Wemb = (const float*)d_in[18];
    const float* bemb = (const float*)d_in[19];
    const float* Wcls = (const float*)d_in[20];
    const float* bcls = (const float*)d_in[21];
    float* out = (float*)d_out;

    // one-time stream/event creation (no device memory involved)
    static cudaStream_t s2 = nullptr;
    static cudaEvent_t ev_fork = nullptr, ev_chunk[4] = {nullptr, nullptr, nullptr, nullptr};
    if (s2 == nullptr) {
        cudaStreamCreateWithFlags(&s2, cudaStreamNonBlocking);
        cudaEventCreateWithFlags(&ev_fork, cudaEventDisableTiming);
        for (int i = 0; i < 4; i++)
            cudaEventCreateWithFlags(&ev_chunk[i], cudaEventDisableTiming);
    }

    const int EB = (EE + 255) / 256;
    const int NB = (NN * 32 + 255) / 256;

    // fork: s2 joins the capture via an event recorded on the main (capture) stream
    cudaEventRecord(ev_fork, 0);
    cudaStreamWaitEvent(s2, ev_fork, 0);

    // s2: weight prep + GEMM in 4 chunks, descending cb (steps consume high k first)
    k_prep_wbf<<<1024, 256, 0, s2>>>(Wxz, Wxh);
    for (int ch = 0; ch < 4; ch++) {
        int cb_base = 24 - ch * 8;                 // 24, 16, 8, 0
        k_gemm<<<dim3(157, 8), 256, 0, s2>>>(x, cb_base);
        cudaEventRecord(ev_chunk[ch], s2);
    }

    // main stream: CSR build + small preps (overlaps chunk 0)
    k_zero<<<256, 256>>>();
    k_hist<<<EB, 256>>>(ei);
    k_scan<<<1, 1024>>>();
    k_scatter<<<EB, 256>>>(ei);
    k_prep_pq<<<1, 64>>>(Wemb, bemb, Wcls);

    // step chain, gated per chunk: chunk ch covers cb in [24-8ch, 31-8ch]
    int bn = 0, b1 = 1, b2 = 2;
    cudaStreamWaitEvent(0, ev_chunk[0], 0);        // Y[24..31] ready
    for (int k = KORD - 1; k >= 1; k--) {
        if (k == 23) cudaStreamWaitEvent(0, ev_chunk[1], 0);   // Y[16..23]
        if (k == 15) cudaStreamWaitEvent(0, ev_chunk[2], 0);   // Y[8..15]
        if (k == 7)  cudaStreamWaitEvent(0, ev_chunk[3], 0);   // Y[0..7]
        k_cheb_step<<<NB, 256>>>(k, bn, b1, b2);
        int t = b2; b2 = b1; b1 = bn; bn = t;
    }
    k_cheb_final<<<NB, 256>>>(b1, b2, bxz, bhz, bxh, bhh);
    k_xp<<<NB, 256>>>(Wgat, asrc, adst);
    k_gat<<<NB, 256>>>(bgat);
    k_out<<<EB, 256>>>(ei, bcls, out);
}